// round 2
// baseline (speedup 1.0000x reference)
#include <cuda_runtime.h>
#include <cuda_bf16.h>
#include <math.h>

#define NN 512
#define NBATCH 128
#define EPS 1e-8f
#define S_CAP 312
#define PK_CAP ((S_CAP*(S_CAP+1))/2)      /* 48828 floats = 195312 B */
#define PK_FULL ((NN*(NN+1))/2)           /* 131328 floats */

// ---------------- device scratch (no allocations allowed) ----------------
__device__ float g_L[NN*NN];       // L = B^T B + eps I (full symmetric)
__device__ float g_Z[NN*NN];       // Z = L + I, Cholesky-factored in place (lower)
__device__ float g_zpart[8];       // per-panel logdet pieces of Z
__device__ float g_bres[NBATCH];   // per-batch logdet(L[S,S])
__device__ float g_fbA[(size_t)NBATCH * PK_FULL]; // fallback packed scratch (s > S_CAP)

// =====================================================================
// K1: L = B^T B + eps I ; Z = L + I.  8x8 grid of 64x64 tiles, 256 thr.
// =====================================================================
__global__ __launch_bounds__(256) void k_gemm(const float* __restrict__ B)
{
    __shared__ float SA[16][64];
    __shared__ float SB[16][64];
    const int tid = threadIdx.x;
    const int tx = tid & 15, ty = tid >> 4;
    const int i0 = blockIdx.y * 64, j0 = blockIdx.x * 64;

    float acc[4][4];
#pragma unroll
    for (int r = 0; r < 4; ++r)
#pragma unroll
        for (int c = 0; c < 4; ++c) acc[r][c] = 0.f;

    for (int kc = 0; kc < NN; kc += 16) {
        for (int e = tid; e < 16*64; e += 256) {
            int kk = e >> 6, ii = e & 63;
            SA[kk][ii] = B[(kc+kk)*NN + i0 + ii];
            SB[kk][ii] = B[(kc+kk)*NN + j0 + ii];
        }
        __syncthreads();
#pragma unroll
        for (int kk = 0; kk < 16; ++kk) {
            float a[4], bb[4];
#pragma unroll
            for (int r = 0; r < 4; ++r) a[r]  = SA[kk][ty*4 + r];
#pragma unroll
            for (int c = 0; c < 4; ++c) bb[c] = SB[kk][tx*4 + c];
#pragma unroll
            for (int r = 0; r < 4; ++r)
#pragma unroll
                for (int c = 0; c < 4; ++c) acc[r][c] += a[r] * bb[c];
        }
        __syncthreads();
    }
#pragma unroll
    for (int r = 0; r < 4; ++r)
#pragma unroll
        for (int c = 0; c < 4; ++c) {
            int gi = i0 + ty*4 + r, gj = j0 + tx*4 + c;
            float v = acc[r][c] + ((gi == gj) ? EPS : 0.f);
            g_L[gi*NN + gj] = v;
            g_Z[gi*NN + gj] = v + ((gi == gj) ? 1.f : 0.f);
        }
}

// =====================================================================
// Z chain: blocked Cholesky of g_Z. Panel of 64 columns in smem (1 CTA),
// then rank-64 trailing update on 64x64 blocks (many CTAs).
// =====================================================================
__global__ __launch_bounds__(256) void k_zpanel(int p)
{
    extern __shared__ float T[];              // nr x 65 (padded rows)
    const int nr = NN - 64*p;
    const int tid = threadIdx.x, warp = tid >> 5, lane = tid & 31;

    // load panel: local row r = global 64p+r, cols 64p..64p+63
    for (int r = warp; r < nr; r += 8) {
        const float* src = &g_Z[(64*p + r)*NN + 64*p];
        float* dst = &T[r*65];
        for (int j = lane; j < 64; j += 32) dst[j] = src[j];
    }
    __syncthreads();

    float lsum = 0.f;
    for (int j = 0; j < 64; ++j) {
        float d = sqrtf(T[j*65 + j]);         // all threads read before any write
        float inv = 1.f / d;
        for (int i = j+1+tid; i < nr; i += 256)
            T[i*65 + j] *= inv;
        __syncthreads();
        if (tid == 0) { T[j*65 + j] = d; lsum += logf(d); }  // nobody reads (j,j) now
        for (int i = j+1+warp; i < nr; i += 8) {
            float ci = T[i*65 + j];
            int kmax = (i < 63) ? i : 63;
            for (int k = j+1+lane; k <= kmax; k += 32)
                T[i*65 + k] -= ci * T[k*65 + j];
        }
        __syncthreads();
    }

    // write back lower part of panel
    for (int r = warp; r < nr; r += 8) {
        float* dst = &g_Z[(64*p + r)*NN + 64*p];
        int jmax = (r < 63) ? r : 63;
        for (int j = lane; j <= jmax; j += 32) dst[j] = T[r*65 + j];
    }
    if (tid == 0) g_zpart[p] = 2.f * lsum;
}

__global__ __launch_bounds__(256) void k_ztrail(int p)
{
    __shared__ float As[64][65];
    __shared__ float Bs[64][65];
    const int t = p + 1;
    int l = blockIdx.x, bi = 0, bj = 0;
    for (int q = t; q <= 7; ++q) {            // decode lower-tri block (bi,bj)
        int c = 8 - q;
        if (l < c) { bj = q; bi = q + l; break; }
        l -= c;
    }
    const int tid = threadIdx.x;
    const int tx = tid & 15, ty = tid >> 4;

    for (int e = tid; e < 64*64; e += 256) {
        int i = e >> 6, k = e & 63;
        As[i][k] = g_Z[(64*bi + i)*NN + 64*p + k];
    }
    for (int e = tid; e < 64*64; e += 256) {
        int i = e >> 6, k = e & 63;
        Bs[i][k] = g_Z[(64*bj + i)*NN + 64*p + k];
    }
    __syncthreads();

    float acc[4][4];
#pragma unroll
    for (int r = 0; r < 4; ++r)
#pragma unroll
        for (int c = 0; c < 4; ++c) acc[r][c] = 0.f;

    for (int k = 0; k < 64; ++k) {
        float a[4], bb[4];
#pragma unroll
        for (int r = 0; r < 4; ++r) a[r]  = As[ty*4 + r][k];
#pragma unroll
        for (int c = 0; c < 4; ++c) bb[c] = Bs[tx*4 + c][k];
#pragma unroll
        for (int r = 0; r < 4; ++r)
#pragma unroll
            for (int c = 0; c < 4; ++c) acc[r][c] += a[r] * bb[c];
    }
#pragma unroll
    for (int r = 0; r < 4; ++r)
#pragma unroll
        for (int c = 0; c < 4; ++c)
            g_Z[(64*bi + ty*4 + r)*NN + 64*bj + tx*4 + c] -= acc[r][c];
}

// =====================================================================
// Per-batch: gather active principal submatrix (packed lower) into smem,
// Cholesky it, logdet = 2*sum log diag. One CTA per batch element.
// =====================================================================
__global__ __launch_bounds__(256) void k_batch(const int* __restrict__ x)
{
    extern __shared__ float Ap[];             // packed lower, PK_CAP floats
    __shared__ int   sidx[NN];
    __shared__ float colj[NN];
    __shared__ int   s_sh;

    const int b = blockIdx.x;
    const int tid = threadIdx.x, warp = tid >> 5, lane = tid & 31;

    // build active index list (warp 0, ballot prefix)
    if (tid < 32) {
        int cnt = 0;
        for (int base = 0; base < NN; base += 32) {
            int v = (x[b*NN + base + tid] != 0);
            unsigned m = __ballot_sync(0xffffffffu, v);
            int pos = cnt + __popc(m & ((1u << tid) - 1u));
            if (v) sidx[pos] = base + tid;
            cnt += __popc(m);
        }
        if (tid == 0) s_sh = cnt;
    }
    __syncthreads();
    const int s = s_sh;
    float* A = (s <= S_CAP) ? Ap : &g_fbA[(size_t)b * PK_FULL];

    // gather packed lower submatrix from g_L (L2-resident)
    for (int i = warp; i < s; i += 8) {
        const int gi = sidx[i];
        const float* Lrow = &g_L[gi * NN];
        const int rb = (i * (i + 1)) >> 1;
        for (int j = lane; j <= i; j += 32)
            A[rb + j] = Lrow[sidx[j]];
    }
    __syncthreads();

    float lsum = 0.f;
    for (int j = 0; j < s; ++j) {
        const int dj = ((j * (j + 1)) >> 1) + j;
        float d = sqrtf(A[dj]);               // all read before any write to (j,j)
        float inv = 1.f / d;
        for (int i = j+1+tid; i < s; i += 256) {
            int ri = ((i * (i + 1)) >> 1) + j;
            float v = A[ri] * inv;
            A[ri] = v;
            colj[i] = v;
        }
        __syncthreads();
        if (tid == 0) { A[dj] = d; lsum += logf(d); }
        for (int i = j+1+warp; i < s; i += 8) {
            const float ci = colj[i];
            const int rb = (i * (i + 1)) >> 1;
            for (int k = j+1+lane; k <= i; k += 32)
                A[rb + k] -= ci * colj[k];
        }
        __syncthreads();
    }
    if (tid == 0) g_bres[b] = 2.f * lsum;
}

// =====================================================================
// combine: out[b] = logdet_b - logdet_Z
// =====================================================================
__global__ void k_combine(float* __restrict__ out)
{
    __shared__ float z;
    if (threadIdx.x == 0) {
        float t = 0.f;
        for (int p = 0; p < 8; ++p) t += g_zpart[p];
        z = t;
    }
    __syncthreads();
    if (threadIdx.x < NBATCH)
        out[threadIdx.x] = g_bres[threadIdx.x] - z;
}

// =====================================================================
extern "C" void kernel_launch(void* const* d_in, const int* in_sizes, int n_in,
                              void* d_out, int out_size)
{
    // metadata order: x (int32, 128*512), B (float32, 512*512); defensive swap
    const int* x = (const int*)d_in[0];
    const float* Bm = (const float*)d_in[1];
    if (in_sizes[0] == NN*NN && in_sizes[1] == NBATCH*NN) {
        x  = (const int*)d_in[1];
        Bm = (const float*)d_in[0];
    }
    float* out = (float*)d_out;

    cudaFuncSetAttribute(k_batch,  cudaFuncAttributeMaxDynamicSharedMemorySize, PK_CAP*4);
    cudaFuncSetAttribute(k_zpanel, cudaFuncAttributeMaxDynamicSharedMemorySize, NN*65*4);

    k_gemm<<<dim3(8,8), 256>>>(Bm);
    k_batch<<<NBATCH, 256, PK_CAP*4>>>(x);
    for (int p = 0; p < 8; ++p) {
        int nr = NN - 64*p;
        k_zpanel<<<1, 256, nr*65*4>>>(p);
        int m = 7 - p;
        if (m > 0) k_ztrail<<<m*(m+1)/2, 256>>>(p);
    }
    k_combine<<<1, 128>>>(out);
}

// round 3
// speedup vs baseline: 2.8609x; 2.8609x over previous
#include <cuda_runtime.h>
#include <cuda_bf16.h>
#include <math.h>

#define NN 512
#define NBATCH 128
#define EPS 1e-8f
#define S_CAP 312
#define PK_CAP ((S_CAP*(S_CAP+1))/2)      /* 48828 floats = 195312 B */
#define PK_FULL ((NN*(NN+1))/2)           /* 131328 floats */
#define NT 512                             /* threads in k_batch / k_zpanel */
#define NW (NT/32)

// ---------------- device scratch (no allocations allowed) ----------------
__device__ float g_L[NN*NN];       // L = B^T B + eps I (full symmetric)
__device__ float g_Z[NN*NN];       // Z = L + I, Cholesky-factored in place (lower)
__device__ float g_zpart[8];       // per-panel logdet pieces of Z
__device__ float g_bres[NBATCH];   // per-batch logdet(L[S,S])
__device__ float g_fbA[(size_t)NBATCH * PK_FULL]; // fallback scratch (s > S_CAP; ~never)

// =====================================================================
// K1: L = B^T B + eps I ; Z = L + I.  8x8 grid of 64x64 tiles, 256 thr.
// =====================================================================
__global__ __launch_bounds__(256) void k_gemm(const float* __restrict__ B)
{
    __shared__ float SA[16][64];
    __shared__ float SB[16][64];
    const int tid = threadIdx.x;
    const int tx = tid & 15, ty = tid >> 4;
    const int i0 = blockIdx.y * 64, j0 = blockIdx.x * 64;

    float acc[4][4];
#pragma unroll
    for (int r = 0; r < 4; ++r)
#pragma unroll
        for (int c = 0; c < 4; ++c) acc[r][c] = 0.f;

    for (int kc = 0; kc < NN; kc += 16) {
        for (int e = tid; e < 16*64; e += 256) {
            int kk = e >> 6, ii = e & 63;
            SA[kk][ii] = B[(kc+kk)*NN + i0 + ii];
            SB[kk][ii] = B[(kc+kk)*NN + j0 + ii];
        }
        __syncthreads();
#pragma unroll
        for (int kk = 0; kk < 16; ++kk) {
            float a[4], bb[4];
#pragma unroll
            for (int r = 0; r < 4; ++r) a[r]  = SA[kk][ty*4 + r];
#pragma unroll
            for (int c = 0; c < 4; ++c) bb[c] = SB[kk][tx*4 + c];
#pragma unroll
            for (int r = 0; r < 4; ++r)
#pragma unroll
                for (int c = 0; c < 4; ++c) acc[r][c] += a[r] * bb[c];
        }
        __syncthreads();
    }
#pragma unroll
    for (int r = 0; r < 4; ++r)
#pragma unroll
        for (int c = 0; c < 4; ++c) {
            int gi = i0 + ty*4 + r, gj = j0 + tx*4 + c;
            float v = acc[r][c] + ((gi == gj) ? EPS : 0.f);
            g_L[gi*NN + gj] = v;
            g_Z[gi*NN + gj] = v + ((gi == gj) ? 1.f : 0.f);
        }
}

// =====================================================================
// Per-batch blocked Cholesky of gathered principal submatrix (packed
// lower in dynamic smem). nb=32 blocking:
//   A: warp0 factors 32x32 diag block in registers (shfl rank-1)
//   B: rows below solve vs L11^T, row in registers
//   C: rank-32 SYRK trailing, 4x4 register tiles per lane
// =====================================================================
__global__ __launch_bounds__(NT) void k_batch(const int* __restrict__ x)
{
    extern __shared__ float Ap[];
    __shared__ int   sidx[NN];
    __shared__ float s_inv[32];
    __shared__ int   s_rbD[32];
    __shared__ int   s_sh;

    const int b = blockIdx.x;
    const int tid = threadIdx.x, warp = tid >> 5, lane = tid & 31;

    // active index list (warp 0, ballot prefix)
    if (tid < 32) {
        int cnt = 0;
        for (int base = 0; base < NN; base += 32) {
            int v = (x[b*NN + base + lane] != 0);
            unsigned m = __ballot_sync(0xffffffffu, v);
            int pos = cnt + __popc(m & ((1u << lane) - 1u));
            if (v) sidx[pos] = base + lane;
            cnt += __popc(m);
        }
        if (lane == 0) s_sh = cnt;
    }
    __syncthreads();
    const int s = s_sh;
    float* A = (s <= S_CAP) ? Ap : &g_fbA[(size_t)b * PK_FULL];

    // gather packed lower submatrix from g_L (L2-resident)
    for (int i = warp; i < s; i += NW) {
        const float* Lrow = &g_L[sidx[i] * NN];
        const int rb = (i * (i + 1)) >> 1;
        for (int j = lane; j <= i; j += 32)
            A[rb + j] = Lrow[sidx[j]];
    }
    __syncthreads();

    float lsum = 0.f;   // meaningful on tid 0 only
    for (int j0 = 0; j0 < s; j0 += 32) {
        const int nbj = (s - j0 < 32) ? (s - j0) : 32;
        if (tid < 32 && tid < nbj)
            s_rbD[tid] = (((j0 + tid) * (j0 + tid + 1)) >> 1) + j0;
        __syncthreads();

        // ---- Phase A: warp0 factors diag block in registers ----
        if (warp == 0) {
            const int row = j0 + lane;
            const bool act = (lane < nbj);
            int rbI = 0;
            if (act) rbI = (row * (row + 1)) >> 1;
            float v[32];
#pragma unroll
            for (int k = 0; k < 32; ++k)
                v[k] = (act && k <= lane && k < nbj) ? A[rbI + j0 + k] : 0.f;

            for (int j = 0; j < nbj; ++j) {
                float dj = __shfl_sync(0xffffffffu, v[j], j);
                float d = sqrtf(dj);
                float inv = 1.f / d;
                if (lane == j) { v[j] = d; s_inv[j] = inv; }
                else if (lane > j) v[j] *= inv;
                float cj = (act && lane > j) ? v[j] : 0.f;
                for (int k = j + 1; k < nbj; ++k) {
                    float cjk = __shfl_sync(0xffffffffu, cj, k);
                    if (lane >= k) v[k] -= cj * cjk;
                }
                if (lane == 0) lsum += logf(d);
            }
#pragma unroll
            for (int k = 0; k < 32; ++k)
                if (act && k <= lane && k < nbj) A[rbI + j0 + k] = v[k];
        }
        __syncthreads();

        const int j1 = j0 + 32;
        if (j1 >= s) break;                     // uniform across CTA

        // ---- Phase B: triangular solve rows j1..s-1 (row in regs) ----
        for (int i = j1 + tid; i < s; i += NT) {
            const int rbI = (i * (i + 1)) >> 1;
            float v[32];
#pragma unroll
            for (int j = 0; j < 32; ++j) v[j] = A[rbI + j0 + j];
#pragma unroll
            for (int j = 0; j < 32; ++j) {
                float acc = v[j];
                const int rbD = s_rbD[j];
                for (int m = 0; m < j; ++m) acc -= v[m] * A[rbD + m];
                v[j] = acc * s_inv[j];
            }
#pragma unroll
            for (int j = 0; j < 32; ++j) A[rbI + j0 + j] = v[j];
        }
        __syncthreads();

        // ---- Phase C: SYRK trailing, 4x4 tiles ----
        const int nrows = s - j1;
        const int R = (nrows + 3) >> 2;
        for (int ti = warp; ti < R; ti += NW) {
            const int r0 = j1 + ti * 4;
            int rb_r[4];
#pragma unroll
            for (int q = 0; q < 4; ++q) {
                int r = r0 + q; if (r > s - 1) r = s - 1;
                rb_r[q] = (r * (r + 1)) >> 1;
            }
            for (int kt = lane; kt <= ti; kt += 32) {
                const int c0 = j1 + kt * 4;
                int rb_c[4];
#pragma unroll
                for (int q = 0; q < 4; ++q) {
                    int c = c0 + q; if (c > s - 1) c = s - 1;
                    rb_c[q] = (c * (c + 1)) >> 1;
                }
                float acc[4][4];
#pragma unroll
                for (int qr = 0; qr < 4; ++qr)
#pragma unroll
                    for (int qc = 0; qc < 4; ++qc) acc[qr][qc] = 0.f;
#pragma unroll
                for (int j = 0; j < 32; ++j) {
                    float a[4], bb[4];
#pragma unroll
                    for (int q = 0; q < 4; ++q) a[q]  = A[rb_r[q] + j0 + j];
#pragma unroll
                    for (int q = 0; q < 4; ++q) bb[q] = A[rb_c[q] + j0 + j];
#pragma unroll
                    for (int qr = 0; qr < 4; ++qr)
#pragma unroll
                        for (int qc = 0; qc < 4; ++qc)
                            acc[qr][qc] += a[qr] * bb[qc];
                }
#pragma unroll
                for (int qr = 0; qr < 4; ++qr) {
                    const int r = r0 + qr;
#pragma unroll
                    for (int qc = 0; qc < 4; ++qc) {
                        const int c = c0 + qc;
                        if (r < s && c <= r)
                            A[rb_r[qr] + c] -= acc[qr][qc];
                    }
                }
            }
        }
        __syncthreads();
    }
    if (tid == 0) g_bres[b] = 2.f * lsum;
}

// =====================================================================
// Z chain: blocked Cholesky of g_Z (512). Panel of 64 cols in smem with
// internal nb=32 blocking, then multi-CTA 64x64 trailing SYRK.
// =====================================================================
__global__ __launch_bounds__(NT) void k_zpanel(int p)
{
    extern __shared__ float T[];              // nr x 65
    __shared__ float s_inv[32];
    const int nr = NN - 64 * p;               // >= 64
    const int tid = threadIdx.x, warp = tid >> 5, lane = tid & 31;

    for (int r = warp; r < nr; r += NW) {
        const float* src = &g_Z[(64*p + r)*NN + 64*p];
        float* dst = &T[r*65];
        for (int j = lane; j < 64; j += 32) dst[j] = src[j];
    }
    __syncthreads();

    float lsum = 0.f;
    for (int cb = 0; cb < 64; cb += 32) {
        // ---- Phase A: warp0, diag block in registers ----
        if (warp == 0) {
            float v[32];
#pragma unroll
            for (int k = 0; k < 32; ++k)
                v[k] = (k <= lane) ? T[(cb+lane)*65 + cb + k] : 0.f;
            for (int j = 0; j < 32; ++j) {
                float dj = __shfl_sync(0xffffffffu, v[j], j);
                float d = sqrtf(dj);
                float inv = 1.f / d;
                if (lane == j) { v[j] = d; s_inv[j] = inv; }
                else if (lane > j) v[j] *= inv;
                float cj = (lane > j) ? v[j] : 0.f;
                for (int k = j + 1; k < 32; ++k) {
                    float cjk = __shfl_sync(0xffffffffu, cj, k);
                    if (lane >= k) v[k] -= cj * cjk;
                }
                if (lane == 0) lsum += logf(d);
            }
#pragma unroll
            for (int k = 0; k < 32; ++k)
                if (k <= lane) T[(cb+lane)*65 + cb + k] = v[k];
        }
        __syncthreads();

        const int r1 = cb + 32;
        // ---- Phase B: rows r1..nr-1 solve cols cb..cb+31 ----
        for (int i = r1 + tid; i < nr; i += NT) {
            float* row = &T[i*65 + cb];
            float v[32];
#pragma unroll
            for (int j = 0; j < 32; ++j) v[j] = row[j];
#pragma unroll
            for (int j = 0; j < 32; ++j) {
                float acc = v[j];
                const float* dr = &T[(cb+j)*65 + cb];
                for (int m = 0; m < j; ++m) acc -= v[m] * dr[m];
                v[j] = acc * s_inv[j];
            }
#pragma unroll
            for (int j = 0; j < 32; ++j) row[j] = v[j];
        }
        __syncthreads();

        // ---- Phase C (cb==0): rank-32 update of cols 32..63 ----
        if (cb == 0) {
            const int nrows = nr - 32;
            const int RT = (nrows + 15) >> 4;   // 16-row supertiles per warp
            const int sub = lane >> 3;          // 0..3
            const int ktc = lane & 7;           // 0..7
            for (int ti = warp; ti < RT; ti += NW) {
                const int r0 = 32 + ti*16 + sub*4;
                const int c0 = 32 + ktc*4;
                float acc[4][4];
#pragma unroll
                for (int qr = 0; qr < 4; ++qr)
#pragma unroll
                    for (int qc = 0; qc < 4; ++qc) acc[qr][qc] = 0.f;
#pragma unroll
                for (int j = 0; j < 32; ++j) {
                    float a[4], bb[4];
#pragma unroll
                    for (int q = 0; q < 4; ++q) {
                        int r = r0 + q; if (r > nr - 1) r = nr - 1;
                        a[q] = T[r*65 + j];
                    }
#pragma unroll
                    for (int q = 0; q < 4; ++q) bb[q] = T[(c0+q)*65 + j];
#pragma unroll
                    for (int qr = 0; qr < 4; ++qr)
#pragma unroll
                        for (int qc = 0; qc < 4; ++qc)
                            acc[qr][qc] += a[qr] * bb[qc];
                }
#pragma unroll
                for (int qr = 0; qr < 4; ++qr) {
                    const int r = r0 + qr;
#pragma unroll
                    for (int qc = 0; qc < 4; ++qc) {
                        const int c = c0 + qc;
                        if (r < nr && c <= r)
                            T[r*65 + c] -= acc[qr][qc];
                    }
                }
            }
        }
        __syncthreads();
    }

    for (int r = warp; r < nr; r += NW) {
        float* dst = &g_Z[(64*p + r)*NN + 64*p];
        int jmax = (r < 63) ? r : 63;
        for (int j = lane; j <= jmax; j += 32) dst[j] = T[r*65 + j];
    }
    if (tid == 0) g_zpart[p] = 2.f * lsum;
}

__global__ __launch_bounds__(256) void k_ztrail(int p)
{
    __shared__ float As[64][65];
    __shared__ float Bs[64][65];
    int l = blockIdx.x, bi = 0, bj = 0;
    for (int q = p + 1; q <= 7; ++q) {
        int c = 8 - q;
        if (l < c) { bj = q; bi = q + l; break; }
        l -= c;
    }
    const int tid = threadIdx.x;
    const int tx = tid & 15, ty = tid >> 4;

    for (int e = tid; e < 64*64; e += 256) {
        int i = e >> 6, k = e & 63;
        As[i][k] = g_Z[(64*bi + i)*NN + 64*p + k];
    }
    for (int e = tid; e < 64*64; e += 256) {
        int i = e >> 6, k = e & 63;
        Bs[i][k] = g_Z[(64*bj + i)*NN + 64*p + k];
    }
    __syncthreads();

    float acc[4][4];
#pragma unroll
    for (int r = 0; r < 4; ++r)
#pragma unroll
        for (int c = 0; c < 4; ++c) acc[r][c] = 0.f;

    for (int k = 0; k < 64; ++k) {
        float a[4], bb[4];
#pragma unroll
        for (int r = 0; r < 4; ++r) a[r]  = As[ty*4 + r][k];
#pragma unroll
        for (int c = 0; c < 4; ++c) bb[c] = Bs[tx*4 + c][k];
#pragma unroll
        for (int r = 0; r < 4; ++r)
#pragma unroll
            for (int c = 0; c < 4; ++c) acc[r][c] += a[r] * bb[c];
    }
#pragma unroll
    for (int r = 0; r < 4; ++r)
#pragma unroll
        for (int c = 0; c < 4; ++c)
            g_Z[(64*bi + ty*4 + r)*NN + 64*bj + tx*4 + c] -= acc[r][c];
}

// =====================================================================
__global__ void k_combine(float* __restrict__ out)
{
    __shared__ float z;
    if (threadIdx.x == 0) {
        float t = 0.f;
        for (int p = 0; p < 8; ++p) t += g_zpart[p];
        z = t;
    }
    __syncthreads();
    if (threadIdx.x < NBATCH)
        out[threadIdx.x] = g_bres[threadIdx.x] - z;
}

// =====================================================================
extern "C" void kernel_launch(void* const* d_in, const int* in_sizes, int n_in,
                              void* d_out, int out_size)
{
    const int* x = (const int*)d_in[0];
    const float* Bm = (const float*)d_in[1];
    if (in_sizes[0] == NN*NN && in_sizes[1] == NBATCH*NN) {
        x  = (const int*)d_in[1];
        Bm = (const float*)d_in[0];
    }
    float* out = (float*)d_out;

    cudaFuncSetAttribute(k_batch,  cudaFuncAttributeMaxDynamicSharedMemorySize, PK_CAP*4);
    cudaFuncSetAttribute(k_zpanel, cudaFuncAttributeMaxDynamicSharedMemorySize, NN*65*4);

    k_gemm<<<dim3(8,8), 256>>>(Bm);
    k_batch<<<NBATCH, NT, PK_CAP*4>>>(x);
    for (int p = 0; p < 8; ++p) {
        int nr = NN - 64*p;
        k_zpanel<<<1, NT, nr*65*4>>>(p);
        int m = 7 - p;
        if (m > 0) k_ztrail<<<m*(m+1)/2, 256>>>(p);
    }
    k_combine<<<1, 128>>>(out);
}